// round 8
// baseline (speedup 1.0000x reference)
#include <cuda_runtime.h>
#include <cstdint>

#define N_NODES 50000
#define N_EDGES 800000
#define DIM 128
#define DIM4 32
#define AS 132      // A smem stride (uint32/tf32)
#define WS 136      // W smem stride (uint32/tf32)
#define TM 64       // gemm tile rows
#define GEMM_T 512  // gemm threads

// Scratch (allocation-free: __device__ globals)
__device__ float g_h[N_NODES * DIM];    // gemm output (both layers)
__device__ float g_z[N_NODES * DIM];    // layer-1 activations
__device__ float g_deg[N_NODES];
__device__ float g_dinv[N_NODES];
__device__ int   g_cnt[N_NODES];
__device__ int   g_cursor[N_NODES];
__device__ int   g_rowstart[N_NODES + 1];
__device__ int   g_blocksums[128];
__device__ int2  g_edges[N_EDGES];

// ---------------------------------------------------------------------------
__global__ void k_init(int n) {
    int i = blockIdx.x * blockDim.x + threadIdx.x;
    if (i < n) { g_deg[i] = 1.0f; g_cnt[i] = 0; g_cursor[i] = 0; }
}

__global__ void k_count(const int* __restrict__ dst, const float* __restrict__ ew, int e) {
    int i = blockIdx.x * blockDim.x + threadIdx.x;
    if (i < e) {
        int d = dst[i];
        atomicAdd(&g_deg[d], ew[i]);
        atomicAdd(&g_cnt[d], 1);
    }
}

// ---------------------------------------------------------------------------
__device__ __forceinline__ int warp_incl_scan(int x, int lane) {
    #pragma unroll
    for (int o = 1; o < 32; o <<= 1) {
        int y = __shfl_up_sync(0xffffffffu, x, o);
        if (lane >= o) x += y;
    }
    return x;
}

// scan phase 1 (+ fused dinv)
__global__ void k_scan1(int n) {
    __shared__ int warpsums[32];
    const int lane = threadIdx.x & 31;
    const int warp = threadIdx.x >> 5;
    int i = blockIdx.x * 1024 + threadIdx.x;
    if (i < n) g_dinv[i] = rsqrtf(g_deg[i]);
    int v = (i < n) ? g_cnt[i] : 0;
    int x = warp_incl_scan(v, lane);
    if (lane == 31) warpsums[warp] = x;
    __syncthreads();
    if (threadIdx.x < 32) {
        int s = warpsums[threadIdx.x];
        int xs = warp_incl_scan(s, threadIdx.x);
        warpsums[threadIdx.x] = xs - s;
    }
    __syncthreads();
    int excl = (x - v) + warpsums[warp];
    if (i < n) g_rowstart[i] = excl;
    if (threadIdx.x == 1023) g_blocksums[blockIdx.x] = excl + v;
}

__global__ void k_scan2(int nblocks, int n, int e) {
    __shared__ int tmp[128];
    const int lane = threadIdx.x & 31;
    if (threadIdx.x < 128) tmp[threadIdx.x] = (threadIdx.x < nblocks) ? g_blocksums[threadIdx.x] : 0;
    __syncthreads();
    if (threadIdx.x < 32) {
        int carry = 0;
        for (int c = 0; c < 128; c += 32) {
            int v = tmp[c + lane];
            int x = warp_incl_scan(v, lane);
            tmp[c + lane] = (x - v) + carry;
            carry += __shfl_sync(0xffffffffu, x, 31);
        }
    }
    __syncthreads();
    if (threadIdx.x < 128 && threadIdx.x < nblocks) g_blocksums[threadIdx.x] = tmp[threadIdx.x];
    if (threadIdx.x == 0) g_rowstart[n] = e;
}

__global__ void k_scan3(int n) {
    int i = blockIdx.x * blockDim.x + threadIdx.x;
    if (i < n) g_rowstart[i] += g_blocksums[i >> 10];
}

__global__ void k_reorder(const int* __restrict__ src, const int* __restrict__ dst,
                          const float* __restrict__ ew, int e) {
    int i = blockIdx.x * blockDim.x + threadIdx.x;
    if (i < e) {
        int s = src[i];
        int d = dst[i];
        float nrm = g_dinv[s] * ew[i] * g_dinv[d];
        int p = g_rowstart[d] + atomicAdd(&g_cursor[d], 1);
        g_edges[p] = make_int2(s, __float_as_int(nrm));
    }
}

// ---------------------------------------------------------------------------
// tf32 tensor GEMM v4: TM=64 tile, single A buffer (103.4KB smem),
// 2 blocks/SM co-resident (block-level double buffering), 512 thr / 16 warps
// in 4m x 4n layout: warp tile 16x32. A converted to tf32 at staging so the
// fragment path is pure LDS -> HMMA.
// ---------------------------------------------------------------------------
__device__ __forceinline__ uint32_t f2tf32(float v) {
    uint32_t o;
    asm("cvt.rna.tf32.f32 %0, %1;" : "=r"(o) : "f"(v));
    return o;
}

__device__ __forceinline__ void mma_tf32(float* c, const uint32_t* a,
                                         uint32_t b0, uint32_t b1) {
    asm volatile(
        "mma.sync.aligned.m16n8k8.row.col.f32.tf32.tf32.f32 "
        "{%0,%1,%2,%3}, {%4,%5,%6,%7}, {%8,%9}, {%0,%1,%2,%3};"
        : "+f"(c[0]), "+f"(c[1]), "+f"(c[2]), "+f"(c[3])
        : "r"(a[0]), "r"(a[1]), "r"(a[2]), "r"(a[3]), "r"(b0), "r"(b1));
}

__global__ void __launch_bounds__(GEMM_T, 2)
k_gemm(const float* __restrict__ in, const float* __restrict__ W,
       float* __restrict__ out, int n) {
    extern __shared__ uint32_t smem[];
    uint32_t* Ws = smem;                    // [128][WS] tf32
    uint32_t* As = smem + DIM * WS;         // [64][AS] tf32

    const int tid  = threadIdx.x;
    const int lane = tid & 31;
    const int warp = tid >> 5;
    const int warp_m = (warp & 3) * 16;
    const int warp_n = (warp >> 2) * 32;
    const int ntiles = (n + TM - 1) / TM;

    // stage W -> tf32 smem (4096 float4 / 512 thr = 8 per thread)
    for (int i = tid; i < DIM * DIM4; i += GEMM_T) {
        int k = i >> 5, c4 = (i & 31) << 2;
        float4 v = ((const float4*)W)[i];
        uint32_t* p = Ws + k * WS + c4;
        p[0] = f2tf32(v.x); p[1] = f2tf32(v.y); p[2] = f2tf32(v.z); p[3] = f2tf32(v.w);
    }

    const int ar  = lane >> 2;
    const int akc = lane & 3;

    for (int t = blockIdx.x; t < ntiles; t += gridDim.x) {
        int row0 = t * TM;
        __syncthreads();   // As free (also covers W staging, 1st iter)
        // stage A tile (64 rows), converting to tf32 (2048 float4 / 512 = 4/thr)
        for (int i = tid; i < TM * DIM4; i += GEMM_T) {
            int r = i >> 5, c4 = (i & 31) << 2;
            uint32_t* p = As + r * AS + c4;
            if (row0 + r < n) {
                float4 v = ((const float4*)(in + (size_t)(row0 + r) * DIM))[i & 31];
                p[0] = f2tf32(v.x); p[1] = f2tf32(v.y); p[2] = f2tf32(v.z); p[3] = f2tf32(v.w);
            } else {
                p[0] = 0u; p[1] = 0u; p[2] = 0u; p[3] = 0u;
            }
        }
        __syncthreads();

        float acc[4][4];
        #pragma unroll
        for (int nt = 0; nt < 4; nt++)
            #pragma unroll
            for (int q = 0; q < 4; q++) acc[nt][q] = 0.0f;

        #pragma unroll
        for (int ks = 0; ks < 16; ks++) {
            const int k0 = ks * 8;
            uint32_t a[4];
            {
                int r = warp_m + ar;
                a[0] = As[r * AS + k0 + akc];
                a[1] = As[(r + 8) * AS + k0 + akc];
                a[2] = As[r * AS + k0 + akc + 4];
                a[3] = As[(r + 8) * AS + k0 + akc + 4];
            }
            #pragma unroll
            for (int nt = 0; nt < 4; nt++) {
                int bn = warp_n + nt * 8 + (lane >> 2);
                int bk = k0 + (lane & 3);
                uint32_t b0 = Ws[bk * WS + bn];
                uint32_t b1 = Ws[(bk + 4) * WS + bn];
                mma_tf32(acc[nt], a, b0, b1);
            }
        }

        int rbase = row0 + warp_m + (lane >> 2);
        #pragma unroll
        for (int nt = 0; nt < 4; nt++) {
            int col = warp_n + nt * 8 + 2 * (lane & 3);
            if (rbase < n)
                *(float2*)(out + (size_t)rbase * DIM + col) =
                    make_float2(acc[nt][0], acc[nt][1]);
            if (rbase + 8 < n)
                *(float2*)(out + (size_t)(rbase + 8) * DIM + col) =
                    make_float2(acc[nt][2], acc[nt][3]);
        }
    }
}

// ---------------------------------------------------------------------------
// Gather-aggregate (no atomics), unroll 8.
// ---------------------------------------------------------------------------
__global__ void k_agg(const float* __restrict__ h, const float* __restrict__ b,
                      float* __restrict__ out, int n) {
    int t = blockIdx.x * blockDim.x + threadIdx.x;
    int node = t >> 5;
    int lane = t & 31;
    if (node >= n) return;

    int beg = g_rowstart[node];
    int end = g_rowstart[node + 1];

    float di = g_dinv[node];
    float sl = di * di;
    float4 hv = ((const float4*)(h + (size_t)node * DIM))[lane];
    float4 acc = make_float4(hv.x * sl, hv.y * sl, hv.z * sl, hv.w * sl);

    for (int j0 = beg; j0 < end; j0 += 32) {
        int m = end - j0; if (m > 32) m = 32;
        int2 ed = make_int2(0, 0);
        if (lane < m) ed = g_edges[j0 + lane];

        int k = 0;
        for (; k + 8 <= m; k += 8) {
            int s[8]; float nr[8];
            #pragma unroll
            for (int q = 0; q < 8; q++) {
                s[q]  = __shfl_sync(0xffffffffu, ed.x, k + q);
                nr[q] = __int_as_float(__shfl_sync(0xffffffffu, ed.y, k + q));
            }
            float4 v[8];
            #pragma unroll
            for (int q = 0; q < 8; q++)
                v[q] = ((const float4*)(h + (size_t)s[q] * DIM))[lane];
            #pragma unroll
            for (int q = 0; q < 8; q++) {
                acc.x = fmaf(nr[q], v[q].x, acc.x);
                acc.y = fmaf(nr[q], v[q].y, acc.y);
                acc.z = fmaf(nr[q], v[q].z, acc.z);
                acc.w = fmaf(nr[q], v[q].w, acc.w);
            }
        }
        for (; k < m; k++) {
            int   s0 = __shfl_sync(0xffffffffu, ed.x, k);
            float n0 = __int_as_float(__shfl_sync(0xffffffffu, ed.y, k));
            float4 v0 = ((const float4*)(h + (size_t)s0 * DIM))[lane];
            acc.x = fmaf(n0, v0.x, acc.x); acc.y = fmaf(n0, v0.y, acc.y);
            acc.z = fmaf(n0, v0.z, acc.z); acc.w = fmaf(n0, v0.w, acc.w);
        }
    }

    float4 bv = ((const float4*)b)[lane];
    float4 o;
    o.x = fmaxf(acc.x + bv.x, 0.0f);
    o.y = fmaxf(acc.y + bv.y, 0.0f);
    o.z = fmaxf(acc.z + bv.z, 0.0f);
    o.w = fmaxf(acc.w + bv.w, 0.0f);
    ((float4*)(out + (size_t)node * DIM))[lane] = o;
}

// ---------------------------------------------------------------------------
extern "C" void kernel_launch(void* const* d_in, const int* in_sizes, int n_in,
                              void* d_out, int out_size) {
    const float* x   = (const float*)d_in[0];
    const int*   ei  = (const int*)d_in[1];
    const float* ew  = (const float*)d_in[2];
    const float* W1  = (const float*)d_in[3];
    const float* b1  = (const float*)d_in[4];
    const float* W2  = (const float*)d_in[5];
    const float* b2  = (const float*)d_in[6];
    float* out = (float*)d_out;

    const int n = in_sizes[0] / DIM;
    const int e = in_sizes[2];
    const int* src = ei;
    const int* dst = ei + e;

    const int T = 256;
    const int gN = (n + T - 1) / T;
    const int gE = (e + T - 1) / T;
    const int gW = (n * 32 + T - 1) / T;
    const int nScanBlk = (n + 1023) / 1024;

    static cudaStream_t s2 = nullptr;
    static cudaEvent_t ev_fork = nullptr, ev_join = nullptr;
    static bool init_done = false;
    const int GEMM_SMEM = (DIM * WS + TM * AS) * sizeof(uint32_t);  // 103.4KB
    if (!init_done) {
        cudaFuncSetAttribute(k_gemm, cudaFuncAttributeMaxDynamicSharedMemorySize, GEMM_SMEM);
        cudaStreamCreateWithFlags(&s2, cudaStreamNonBlocking);
        cudaEventCreateWithFlags(&ev_fork, cudaEventDisableTiming);
        cudaEventCreateWithFlags(&ev_join, cudaEventDisableTiming);
        init_done = true;
    }
    const int GEMM_GRID = 296;   // 2 blocks per SM

    float* g_h_p;  cudaGetSymbolAddress((void**)&g_h_p, g_h);
    float* g_z_p;  cudaGetSymbolAddress((void**)&g_z_p, g_z);

    // fork: CSR build on s2, GEMM-1 on main
    cudaEventRecord(ev_fork, 0);
    cudaStreamWaitEvent(s2, ev_fork, 0);

    k_init<<<gN, T, 0, s2>>>(n);                    // 0
    k_count<<<gE, T, 0, s2>>>(dst, ew, e);          // 1
    k_scan1<<<nScanBlk, 1024, 0, s2>>>(n);          // 2
    k_gemm<<<GEMM_GRID, GEMM_T, GEMM_SMEM>>>(x, W1, g_h_p, n);  // 3 <- profile target
    k_scan2<<<1, 128, 0, s2>>>(nScanBlk, n, e);     // 4
    k_scan3<<<gN, T, 0, s2>>>(n);                   // 5
    k_reorder<<<gE, T, 0, s2>>>(src, dst, ew, e);   // 6
    cudaEventRecord(ev_join, s2);
    cudaStreamWaitEvent(0, ev_join, 0);

    // serial layer schedule (chunked pipeline regressed; reverted)
    k_agg<<<gW, T>>>(g_h_p, b1, g_z_p, n);
    k_gemm<<<GEMM_GRID, GEMM_T, GEMM_SMEM>>>(g_z_p, W2, g_h_p, n);
    k_agg<<<gW, T>>>(g_h_p, b2, out, n);
}

// round 9
// speedup vs baseline: 1.0369x; 1.0369x over previous
#include <cuda_runtime.h>
#include <cstdint>

#define N_NODES 50000
#define N_EDGES 800000
#define DIM 128
#define DIM4 32
#define AS 132      // A smem stride (floats)
#define WS 136      // W smem stride (floats)
#define TM 128      // gemm tile rows
#define GEMM_T 512  // gemm threads

// Scratch (allocation-free: __device__ globals)
__device__ float g_h[N_NODES * DIM];    // layer-1 gemm output (gather source L1)
__device__ float g_z[N_NODES * DIM];    // layer-1 activations (gemm2 input)
__device__ float g_h2[N_NODES * DIM];   // layer-2 gemm output (gather source L2)
__device__ float g_deg[N_NODES];
__device__ float g_dinv[N_NODES];
__device__ int   g_cnt[N_NODES];
__device__ int   g_cursor[N_NODES];
__device__ int   g_rowstart[N_NODES + 1];
__device__ int   g_blocksums[128];
__device__ int2  g_edges[N_EDGES];

// ---------------------------------------------------------------------------
__global__ void k_init(int n) {
    int i = blockIdx.x * blockDim.x + threadIdx.x;
    if (i < n) { g_deg[i] = 1.0f; g_cnt[i] = 0; g_cursor[i] = 0; }
}

__global__ void k_count(const int* __restrict__ dst, const float* __restrict__ ew, int e) {
    int i = blockIdx.x * blockDim.x + threadIdx.x;
    if (i < e) {
        int d = dst[i];
        atomicAdd(&g_deg[d], ew[i]);
        atomicAdd(&g_cnt[d], 1);
    }
}

// ---------------------------------------------------------------------------
__device__ __forceinline__ int warp_incl_scan(int x, int lane) {
    #pragma unroll
    for (int o = 1; o < 32; o <<= 1) {
        int y = __shfl_up_sync(0xffffffffu, x, o);
        if (lane >= o) x += y;
    }
    return x;
}

// scan phase 1 (+ fused dinv)
__global__ void k_scan1(int n) {
    __shared__ int warpsums[32];
    const int lane = threadIdx.x & 31;
    const int warp = threadIdx.x >> 5;
    int i = blockIdx.x * 1024 + threadIdx.x;
    if (i < n) g_dinv[i] = rsqrtf(g_deg[i]);
    int v = (i < n) ? g_cnt[i] : 0;
    int x = warp_incl_scan(v, lane);
    if (lane == 31) warpsums[warp] = x;
    __syncthreads();
    if (threadIdx.x < 32) {
        int s = warpsums[threadIdx.x];
        int xs = warp_incl_scan(s, threadIdx.x);
        warpsums[threadIdx.x] = xs - s;
    }
    __syncthreads();
    int excl = (x - v) + warpsums[warp];
    if (i < n) g_rowstart[i] = excl;
    if (threadIdx.x == 1023) g_blocksums[blockIdx.x] = excl + v;
}

__global__ void k_scan2(int nblocks, int n, int e) {
    __shared__ int tmp[128];
    const int lane = threadIdx.x & 31;
    if (threadIdx.x < 128) tmp[threadIdx.x] = (threadIdx.x < nblocks) ? g_blocksums[threadIdx.x] : 0;
    __syncthreads();
    if (threadIdx.x < 32) {
        int carry = 0;
        for (int c = 0; c < 128; c += 32) {
            int v = tmp[c + lane];
            int x = warp_incl_scan(v, lane);
            tmp[c + lane] = (x - v) + carry;
            carry += __shfl_sync(0xffffffffu, x, 31);
        }
    }
    __syncthreads();
    if (threadIdx.x < 128 && threadIdx.x < nblocks) g_blocksums[threadIdx.x] = tmp[threadIdx.x];
    if (threadIdx.x == 0) g_rowstart[n] = e;
}

__global__ void k_scan3(int n) {
    int i = blockIdx.x * blockDim.x + threadIdx.x;
    if (i < n) g_rowstart[i] += g_blocksums[i >> 10];
}

__global__ void k_reorder(const int* __restrict__ src, const int* __restrict__ dst,
                          const float* __restrict__ ew, int e) {
    int i = blockIdx.x * blockDim.x + threadIdx.x;
    if (i < e) {
        int s = src[i];
        int d = dst[i];
        float nrm = g_dinv[s] * ew[i] * g_dinv[d];
        int p = g_rowstart[d] + atomicAdd(&g_cursor[d], 1);
        g_edges[p] = make_int2(s, __float_as_int(nrm));
    }
}

// ---------------------------------------------------------------------------
// tf32 tensor GEMM (v3, best measured 24.3us): 512 thr / 16 warps (8m x 2n),
// warp tile 16x64. Persistent, cp.async double-buffered A, 128x128 block tile.
// ---------------------------------------------------------------------------
__device__ __forceinline__ uint32_t f2tf32(float v) {
    uint32_t o;
    asm("cvt.rna.tf32.f32 %0, %1;" : "=r"(o) : "f"(v));
    return o;
}

__device__ __forceinline__ void mma_tf32(float* c, const uint32_t* a,
                                         uint32_t b0, uint32_t b1) {
    asm volatile(
        "mma.sync.aligned.m16n8k8.row.col.f32.tf32.tf32.f32 "
        "{%0,%1,%2,%3}, {%4,%5,%6,%7}, {%8,%9}, {%0,%1,%2,%3};"
        : "+f"(c[0]), "+f"(c[1]), "+f"(c[2]), "+f"(c[3])
        : "r"(a[0]), "r"(a[1]), "r"(a[2]), "r"(a[3]), "r"(b0), "r"(b1));
}

__device__ __forceinline__ void load_tileA(float* dst, const float* __restrict__ in,
                                           int t, int n, int tid) {
    int row0 = t * TM;
    #pragma unroll 2
    for (int i = tid; i < TM * 32; i += GEMM_T) {
        int r = i >> 5, c = (i & 31) << 2;
        float* d = dst + r * AS + c;
        if (row0 + r < n) {
            uint32_t s = (uint32_t)__cvta_generic_to_shared(d);
            asm volatile("cp.async.cg.shared.global [%0], [%1], 16;"
                         :: "r"(s), "l"(in + (size_t)(row0 + r) * DIM + c));
        } else {
            *(float4*)d = make_float4(0.f, 0.f, 0.f, 0.f);
        }
    }
}

__global__ void __launch_bounds__(GEMM_T, 1)
k_gemm(const float* __restrict__ in, const float* __restrict__ W,
       float* __restrict__ out, int n) {
    extern __shared__ uint32_t smem[];
    uint32_t* Ws = smem;                                  // [128][WS] tf32
    float* As0 = (float*)(smem + DIM * WS);               // [128][AS] fp32
    float* As1 = As0 + TM * AS;

    const int tid  = threadIdx.x;
    const int lane = tid & 31;
    const int warp = tid >> 5;
    const int warp_m = (warp & 7) * 16;
    const int warp_n = (warp >> 3) * 64;
    const int ntiles = (n + TM - 1) / TM;

    // stage W -> tf32 smem
    for (int i = tid; i < DIM * DIM4; i += GEMM_T) {
        int k = i >> 5, c4 = (i & 31) << 2;
        float4 v = ((const float4*)W)[i];
        uint32_t* p = Ws + k * WS + c4;
        p[0] = f2tf32(v.x); p[1] = f2tf32(v.y); p[2] = f2tf32(v.z); p[3] = f2tf32(v.w);
    }

    int t = blockIdx.x;
    if (t < ntiles) {
        load_tileA(As0, in, t, n, tid);
        asm volatile("cp.async.commit_group;");
    }

    int buf = 0;
    const int ar  = lane >> 2;
    const int akc = lane & 3;

    for (; t < ntiles; t += gridDim.x) {
        int tn = t + gridDim.x;
        if (tn < ntiles) {
            load_tileA(buf ? As0 : As1, in, tn, n, tid);
            asm volatile("cp.async.commit_group;");
            asm volatile("cp.async.wait_group 1;");
        } else {
            asm volatile("cp.async.wait_group 0;");
        }
        __syncthreads();   // also covers W staging on first iteration

        const float* A = buf ? As1 : As0;
        float acc[8][4];
        #pragma unroll
        for (int nt = 0; nt < 8; nt++)
            #pragma unroll
            for (int q = 0; q < 4; q++) acc[nt][q] = 0.0f;

        #pragma unroll
        for (int ks = 0; ks < 16; ks++) {
            const int k0 = ks * 8;
            uint32_t a[4];
            {
                int r = warp_m + ar;
                a[0] = f2tf32(A[r * AS + k0 + akc]);
                a[1] = f2tf32(A[(r + 8) * AS + k0 + akc]);
                a[2] = f2tf32(A[r * AS + k0 + akc + 4]);
                a[3] = f2tf32(A[(r + 8) * AS + k0 + akc + 4]);
            }
            #pragma unroll
            for (int nt = 0; nt < 8; nt++) {
                int bn = warp_n + nt * 8 + (lane >> 2);
                int bk = k0 + (lane & 3);
                uint32_t b0 = Ws[bk * WS + bn];
                uint32_t b1 = Ws[(bk + 4) * WS + bn];
                mma_tf32(acc[nt], a, b0, b1);
            }
        }

        int row0 = t * TM;
        int rbase = row0 + warp_m + (lane >> 2);
        #pragma unroll
        for (int nt = 0; nt < 8; nt++) {
            int col = warp_n + nt * 8 + 2 * (lane & 3);
            if (rbase < n)
                *(float2*)(out + (size_t)rbase * DIM + col) =
                    make_float2(acc[nt][0], acc[nt][1]);
            if (rbase + 8 < n)
                *(float2*)(out + (size_t)(rbase + 8) * DIM + col) =
                    make_float2(acc[nt][2], acc[nt][3]);
        }
        __syncthreads();   // tile buffer free for next prefetch
        buf ^= 1;
    }
}

// ---------------------------------------------------------------------------
// Gather-aggregate (no atomics), node range [node0, node1), unroll 8.
// ---------------------------------------------------------------------------
__global__ void k_agg(const float* __restrict__ h, const float* __restrict__ b,
                      float* __restrict__ out, int node0, int node1) {
    int t = blockIdx.x * blockDim.x + threadIdx.x;
    int node = node0 + (t >> 5);
    int lane = t & 31;
    if (node >= node1) return;

    int beg = g_rowstart[node];
    int end = g_rowstart[node + 1];

    float di = g_dinv[node];
    float sl = di * di;
    float4 hv = ((const float4*)(h + (size_t)node * DIM))[lane];
    float4 acc = make_float4(hv.x * sl, hv.y * sl, hv.z * sl, hv.w * sl);

    for (int j0 = beg; j0 < end; j0 += 32) {
        int m = end - j0; if (m > 32) m = 32;
        int2 ed = make_int2(0, 0);
        if (lane < m) ed = g_edges[j0 + lane];

        int k = 0;
        for (; k + 8 <= m; k += 8) {
            int s[8]; float nr[8];
            #pragma unroll
            for (int q = 0; q < 8; q++) {
                s[q]  = __shfl_sync(0xffffffffu, ed.x, k + q);
                nr[q] = __int_as_float(__shfl_sync(0xffffffffu, ed.y, k + q));
            }
            float4 v[8];
            #pragma unroll
            for (int q = 0; q < 8; q++)
                v[q] = ((const float4*)(h + (size_t)s[q] * DIM))[lane];
            #pragma unroll
            for (int q = 0; q < 8; q++) {
                acc.x = fmaf(nr[q], v[q].x, acc.x);
                acc.y = fmaf(nr[q], v[q].y, acc.y);
                acc.z = fmaf(nr[q], v[q].z, acc.z);
                acc.w = fmaf(nr[q], v[q].w, acc.w);
            }
        }
        for (; k < m; k++) {
            int   s0 = __shfl_sync(0xffffffffu, ed.x, k);
            float n0 = __int_as_float(__shfl_sync(0xffffffffu, ed.y, k));
            float4 v0 = ((const float4*)(h + (size_t)s0 * DIM))[lane];
            acc.x = fmaf(n0, v0.x, acc.x); acc.y = fmaf(n0, v0.y, acc.y);
            acc.z = fmaf(n0, v0.z, acc.z); acc.w = fmaf(n0, v0.w, acc.w);
        }
    }

    float4 bv = ((const float4*)b)[lane];
    float4 o;
    o.x = fmaxf(acc.x + bv.x, 0.0f);
    o.y = fmaxf(acc.y + bv.y, 0.0f);
    o.z = fmaxf(acc.z + bv.z, 0.0f);
    o.w = fmaxf(acc.w + bv.w, 0.0f);
    ((float4*)(out + (size_t)node * DIM))[lane] = o;
}

// ---------------------------------------------------------------------------
extern "C" void kernel_launch(void* const* d_in, const int* in_sizes, int n_in,
                              void* d_out, int out_size) {
    const float* x   = (const float*)d_in[0];
    const int*   ei  = (const int*)d_in[1];
    const float* ew  = (const float*)d_in[2];
    const float* W1  = (const float*)d_in[3];
    const float* b1  = (const float*)d_in[4];
    const float* W2  = (const float*)d_in[5];
    const float* b2  = (const float*)d_in[6];
    float* out = (float*)d_out;

    const int n = in_sizes[0] / DIM;
    const int e = in_sizes[2];
    const int* src = ei;
    const int* dst = ei + e;

    const int T = 256;
    const int gN = (n + T - 1) / T;
    const int gE = (e + T - 1) / T;
    const int nScanBlk = (n + 1023) / 1024;

    static cudaStream_t s2 = nullptr;
    static cudaEvent_t ev_fork = nullptr, ev_join = nullptr, ev_g2 = nullptr;
    static cudaEvent_t ev_c0 = nullptr, ev_c1 = nullptr;
    static bool init_done = false;
    const int GEMM_SMEM = (DIM * WS + 2 * TM * AS) * sizeof(uint32_t);  // 200KB
    if (!init_done) {
        cudaFuncSetAttribute(k_gemm, cudaFuncAttributeMaxDynamicSharedMemorySize, GEMM_SMEM);
        cudaStreamCreateWithFlags(&s2, cudaStreamNonBlocking);
        cudaEventCreateWithFlags(&ev_fork, cudaEventDisableTiming);
        cudaEventCreateWithFlags(&ev_join, cudaEventDisableTiming);
        cudaEventCreateWithFlags(&ev_g2, cudaEventDisableTiming);
        cudaEventCreateWithFlags(&ev_c0, cudaEventDisableTiming);
        cudaEventCreateWithFlags(&ev_c1, cudaEventDisableTiming);
        init_done = true;
    }
    const int GEMM_GRID = 148;

    float* g_h_p;   cudaGetSymbolAddress((void**)&g_h_p, g_h);
    float* g_z_p;   cudaGetSymbolAddress((void**)&g_z_p, g_z);
    float* g_h2_p;  cudaGetSymbolAddress((void**)&g_h2_p, g_h2);

    // fork: CSR build on s2, GEMM-1 on main (gemm1 is fully hidden behind CSR)
    cudaEventRecord(ev_fork, 0);
    cudaStreamWaitEvent(s2, ev_fork, 0);

    k_init<<<gN, T, 0, s2>>>(n);
    k_count<<<gE, T, 0, s2>>>(dst, ew, e);
    k_scan1<<<nScanBlk, 1024, 0, s2>>>(n);
    k_gemm<<<GEMM_GRID, GEMM_T, GEMM_SMEM>>>(x, W1, g_h_p, n);
    k_scan2<<<1, 128, 0, s2>>>(nScanBlk, n, e);
    k_scan3<<<gN, T, 0, s2>>>(n);
    k_reorder<<<gE, T, 0, s2>>>(src, dst, ew, e);
    cudaEventRecord(ev_join, s2);
    cudaStreamWaitEvent(0, ev_join, 0);

    // 2-chunk agg1 || gemm2 overlap. gemm2 writes g_h2 (g_h stays intact for
    // agg1's full-range gather).
    const int half = (n + 1) / 2;
    {
        int gWc = (half * 32 + T - 1) / T;
        k_agg<<<gWc, T>>>(g_h_p, b1, g_z_p, 0, half);
        cudaEventRecord(ev_c0, 0);
        cudaStreamWaitEvent(s2, ev_c0, 0);
        k_gemm<<<GEMM_GRID, GEMM_T, GEMM_SMEM, s2>>>(g_z_p, W2, g_h2_p, half);

        int nodes1 = n - half;
        int gWc1 = (nodes1 * 32 + T - 1) / T;
        k_agg<<<gWc1, T>>>(g_h_p, b1, g_z_p, half, n);
        cudaEventRecord(ev_c1, 0);
        cudaStreamWaitEvent(s2, ev_c1, 0);
        k_gemm<<<GEMM_GRID, GEMM_T, GEMM_SMEM, s2>>>(
            g_z_p + (size_t)half * DIM, W2, g_h2_p + (size_t)half * DIM, nodes1);
    }
    cudaEventRecord(ev_g2, s2);
    cudaStreamWaitEvent(0, ev_g2, 0);

    // layer 2 agg (full range), gathers from g_h2
    int gW = (n * 32 + T - 1) / T;
    k_agg<<<gW, T>>>(g_h2_p, b2, out, 0, n);
}

// round 10
// speedup vs baseline: 1.1228x; 1.0829x over previous
#include <cuda_runtime.h>
#include <cstdint>

#define N_NODES 50000
#define N_EDGES 800000
#define DIM 128
#define DIM4 32
#define AS 132      // A smem stride (floats)
#define WS 136      // W smem stride (floats)
#define TM 128      // gemm tile rows
#define GEMM_T 512  // gemm threads

// Scratch (allocation-free: __device__ globals)
__device__ float g_h[N_NODES * DIM];    // layer-1 gemm output (gather source L1)
__device__ float g_z[N_NODES * DIM];    // layer-1 activations (gemm2 input)
__device__ float g_h2[N_NODES * DIM];   // layer-2 gemm output (gather source L2)
__device__ float g_deg[N_NODES];
__device__ float g_dinv[N_NODES];
__device__ int   g_cnt[N_NODES];
__device__ int   g_cursor[N_NODES];
__device__ int   g_rowstart[N_NODES + 1];
__device__ int   g_blocksums[128];
__device__ int2  g_edges[N_EDGES];

// ---------------------------------------------------------------------------
__global__ void k_init(int n) {
    int i = blockIdx.x * blockDim.x + threadIdx.x;
    if (i < n) { g_deg[i] = 1.0f; g_cnt[i] = 0; g_cursor[i] = 0; }
}

__global__ void k_count(const int* __restrict__ dst, const float* __restrict__ ew, int e) {
    int i = blockIdx.x * blockDim.x + threadIdx.x;
    if (i < e) {
        int d = dst[i];
        atomicAdd(&g_deg[d], ew[i]);
        atomicAdd(&g_cnt[d], 1);
    }
}

// ---------------------------------------------------------------------------
__device__ __forceinline__ int warp_incl_scan(int x, int lane) {
    #pragma unroll
    for (int o = 1; o < 32; o <<= 1) {
        int y = __shfl_up_sync(0xffffffffu, x, o);
        if (lane >= o) x += y;
    }
    return x;
}

// scan phase 1 (+ fused dinv)
__global__ void k_scan1(int n) {
    __shared__ int warpsums[32];
    const int lane = threadIdx.x & 31;
    const int warp = threadIdx.x >> 5;
    int i = blockIdx.x * 1024 + threadIdx.x;
    if (i < n) g_dinv[i] = rsqrtf(g_deg[i]);
    int v = (i < n) ? g_cnt[i] : 0;
    int x = warp_incl_scan(v, lane);
    if (lane == 31) warpsums[warp] = x;
    __syncthreads();
    if (threadIdx.x < 32) {
        int s = warpsums[threadIdx.x];
        int xs = warp_incl_scan(s, threadIdx.x);
        warpsums[threadIdx.x] = xs - s;
    }
    __syncthreads();
    int excl = (x - v) + warpsums[warp];
    if (i < n) g_rowstart[i] = excl;
    if (threadIdx.x == 1023) g_blocksums[blockIdx.x] = excl + v;
}

__global__ void k_scan2(int nblocks, int n, int e) {
    __shared__ int tmp[128];
    const int lane = threadIdx.x & 31;
    if (threadIdx.x < 128) tmp[threadIdx.x] = (threadIdx.x < nblocks) ? g_blocksums[threadIdx.x] : 0;
    __syncthreads();
    if (threadIdx.x < 32) {
        int carry = 0;
        for (int c = 0; c < 128; c += 32) {
            int v = tmp[c + lane];
            int x = warp_incl_scan(v, lane);
            tmp[c + lane] = (x - v) + carry;
            carry += __shfl_sync(0xffffffffu, x, 31);
        }
    }
    __syncthreads();
    if (threadIdx.x < 128 && threadIdx.x < nblocks) g_blocksums[threadIdx.x] = tmp[threadIdx.x];
    if (threadIdx.x == 0) g_rowstart[n] = e;
}

__global__ void k_scan3(int n) {
    int i = blockIdx.x * blockDim.x + threadIdx.x;
    if (i < n) g_rowstart[i] += g_blocksums[i >> 10];
}

__global__ void k_reorder(const int* __restrict__ src, const int* __restrict__ dst,
                          const float* __restrict__ ew, int e) {
    int i = blockIdx.x * blockDim.x + threadIdx.x;
    if (i < e) {
        int s = src[i];
        int d = dst[i];
        float nrm = g_dinv[s] * ew[i] * g_dinv[d];
        int p = g_rowstart[d] + atomicAdd(&g_cursor[d], 1);
        g_edges[p] = make_int2(s, __float_as_int(nrm));
    }
}

// ---------------------------------------------------------------------------
// tf32 tensor GEMM (v3): 512 thr / 16 warps (8m x 2n), warp tile 16x64.
// Persistent, cp.async double-buffered A, 128x128 block tile.
// ---------------------------------------------------------------------------
__device__ __forceinline__ uint32_t f2tf32(float v) {
    uint32_t o;
    asm("cvt.rna.tf32.f32 %0, %1;" : "=r"(o) : "f"(v));
    return o;
}

__device__ __forceinline__ void mma_tf32(float* c, const uint32_t* a,
                                         uint32_t b0, uint32_t b1) {
    asm volatile(
        "mma.sync.aligned.m16n8k8.row.col.f32.tf32.tf32.f32 "
        "{%0,%1,%2,%3}, {%4,%5,%6,%7}, {%8,%9}, {%0,%1,%2,%3};"
        : "+f"(c[0]), "+f"(c[1]), "+f"(c[2]), "+f"(c[3])
        : "r"(a[0]), "r"(a[1]), "r"(a[2]), "r"(a[3]), "r"(b0), "r"(b1));
}

__device__ __forceinline__ void load_tileA(float* dst, const float* __restrict__ in,
                                           int t, int n, int tid) {
    int row0 = t * TM;
    #pragma unroll 2
    for (int i = tid; i < TM * 32; i += GEMM_T) {
        int r = i >> 5, c = (i & 31) << 2;
        float* d = dst + r * AS + c;
        if (row0 + r < n) {
            uint32_t s = (uint32_t)__cvta_generic_to_shared(d);
            asm volatile("cp.async.cg.shared.global [%0], [%1], 16;"
                         :: "r"(s), "l"(in + (size_t)(row0 + r) * DIM + c));
        } else {
            *(float4*)d = make_float4(0.f, 0.f, 0.f, 0.f);
        }
    }
}

__global__ void __launch_bounds__(GEMM_T, 1)
k_gemm(const float* __restrict__ in, const float* __restrict__ W,
       float* __restrict__ out, int n) {
    extern __shared__ uint32_t smem[];
    uint32_t* Ws = smem;                                  // [128][WS] tf32
    float* As0 = (float*)(smem + DIM * WS);               // [128][AS] fp32
    float* As1 = As0 + TM * AS;

    const int tid  = threadIdx.x;
    const int lane = tid & 31;
    const int warp = tid >> 5;
    const int warp_m = (warp & 7) * 16;
    const int warp_n = (warp >> 3) * 64;
    const int ntiles = (n + TM - 1) / TM;

    // stage W -> tf32 smem
    for (int i = tid; i < DIM * DIM4; i += GEMM_T) {
        int k = i >> 5, c4 = (i & 31) << 2;
        float4 v = ((const float4*)W)[i];
        uint32_t* p = Ws + k * WS + c4;
        p[0] = f2tf32(v.x); p[1] = f2tf32(v.y); p[2] = f2tf32(v.z); p[3] = f2tf32(v.w);
    }

    int t = blockIdx.x;
    if (t < ntiles) {
        load_tileA(As0, in, t, n, tid);
        asm volatile("cp.async.commit_group;");
    }

    int buf = 0;
    const int ar  = lane >> 2;
    const int akc = lane & 3;

    for (; t < ntiles; t += gridDim.x) {
        int tn = t + gridDim.x;
        if (tn < ntiles) {
            load_tileA(buf ? As0 : As1, in, tn, n, tid);
            asm volatile("cp.async.commit_group;");
            asm volatile("cp.async.wait_group 1;");
        } else {
            asm volatile("cp.async.wait_group 0;");
        }
        __syncthreads();   // also covers W staging on first iteration

        const float* A = buf ? As1 : As0;
        float acc[8][4];
        #pragma unroll
        for (int nt = 0; nt < 8; nt++)
            #pragma unroll
            for (int q = 0; q < 4; q++) acc[nt][q] = 0.0f;

        #pragma unroll
        for (int ks = 0; ks < 16; ks++) {
            const int k0 = ks * 8;
            uint32_t a[4];
            {
                int r = warp_m + ar;
                a[0] = f2tf32(A[r * AS + k0 + akc]);
                a[1] = f2tf32(A[(r + 8) * AS + k0 + akc]);
                a[2] = f2tf32(A[r * AS + k0 + akc + 4]);
                a[3] = f2tf32(A[(r + 8) * AS + k0 + akc + 4]);
            }
            #pragma unroll
            for (int nt = 0; nt < 8; nt++) {
                int bn = warp_n + nt * 8 + (lane >> 2);
                int bk = k0 + (lane & 3);
                uint32_t b0 = Ws[bk * WS + bn];
                uint32_t b1 = Ws[(bk + 4) * WS + bn];
                mma_tf32(acc[nt], a, b0, b1);
            }
        }

        int row0 = t * TM;
        int rbase = row0 + warp_m + (lane >> 2);
        #pragma unroll
        for (int nt = 0; nt < 8; nt++) {
            int col = warp_n + nt * 8 + 2 * (lane & 3);
            if (rbase < n)
                *(float2*)(out + (size_t)rbase * DIM + col) =
                    make_float2(acc[nt][0], acc[nt][1]);
            if (rbase + 8 < n)
                *(float2*)(out + (size_t)(rbase + 8) * DIM + col) =
                    make_float2(acc[nt][2], acc[nt][3]);
        }
        __syncthreads();   // tile buffer free for next prefetch
        buf ^= 1;
    }
}

// ---------------------------------------------------------------------------
// Gather-aggregate v2 (no atomics, NO shuffles): warp-uniform edge loads.
// Edges for a node are CSR-contiguous; all 32 lanes load the same int2
// (1 sector, L1-resident) — removes the 2-shuffles-per-edge serial chain.
// Unroll 8 keeps 8 gather LDG.128 in flight per lane.
// ---------------------------------------------------------------------------
__global__ void k_agg(const float* __restrict__ h, const float* __restrict__ b,
                      float* __restrict__ out, int node0, int node1) {
    int t = blockIdx.x * blockDim.x + threadIdx.x;
    int node = node0 + (t >> 5);
    int lane = t & 31;
    if (node >= node1) return;

    int beg = g_rowstart[node];
    int end = g_rowstart[node + 1];

    float di = g_dinv[node];
    float sl = di * di;
    float4 hv = ((const float4*)(h + (size_t)node * DIM))[lane];
    float4 acc = make_float4(hv.x * sl, hv.y * sl, hv.z * sl, hv.w * sl);

    int j = beg;
    for (; j + 8 <= end; j += 8) {
        int2 ed[8];
        #pragma unroll
        for (int q = 0; q < 8; q++) ed[q] = g_edges[j + q];
        float4 v[8];
        #pragma unroll
        for (int q = 0; q < 8; q++)
            v[q] = ((const float4*)(h + (size_t)ed[q].x * DIM))[lane];
        #pragma unroll
        for (int q = 0; q < 8; q++) {
            float nr = __int_as_float(ed[q].y);
            acc.x = fmaf(nr, v[q].x, acc.x);
            acc.y = fmaf(nr, v[q].y, acc.y);
            acc.z = fmaf(nr, v[q].z, acc.z);
            acc.w = fmaf(nr, v[q].w, acc.w);
        }
    }
    for (; j < end; j++) {
        int2 ed = g_edges[j];
        float nr = __int_as_float(ed.y);
        float4 v = ((const float4*)(h + (size_t)ed.x * DIM))[lane];
        acc.x = fmaf(nr, v.x, acc.x);
        acc.y = fmaf(nr, v.y, acc.y);
        acc.z = fmaf(nr, v.z, acc.z);
        acc.w = fmaf(nr, v.w, acc.w);
    }

    float4 bv = ((const float4*)b)[lane];
    float4 o;
    o.x = fmaxf(acc.x + bv.x, 0.0f);
    o.y = fmaxf(acc.y + bv.y, 0.0f);
    o.z = fmaxf(acc.z + bv.z, 0.0f);
    o.w = fmaxf(acc.w + bv.w, 0.0f);
    ((float4*)(out + (size_t)node * DIM))[lane] = o;
}

// ---------------------------------------------------------------------------
extern "C" void kernel_launch(void* const* d_in, const int* in_sizes, int n_in,
                              void* d_out, int out_size) {
    const float* x   = (const float*)d_in[0];
    const int*   ei  = (const int*)d_in[1];
    const float* ew  = (const float*)d_in[2];
    const float* W1  = (const float*)d_in[3];
    const float* b1  = (const float*)d_in[4];
    const float* W2  = (const float*)d_in[5];
    const float* b2  = (const float*)d_in[6];
    float* out = (float*)d_out;

    const int n = in_sizes[0] / DIM;
    const int e = in_sizes[2];
    const int* src = ei;
    const int* dst = ei + e;

    const int T = 256;
    const int gN = (n + T - 1) / T;
    const int gE = (e + T - 1) / T;
    const int nScanBlk = (n + 1023) / 1024;

    static cudaStream_t s2 = nullptr;
    static cudaEvent_t ev_fork = nullptr, ev_join = nullptr, ev_g2 = nullptr;
    static cudaEvent_t ev_c0 = nullptr, ev_c1 = nullptr;
    static bool init_done = false;
    const int GEMM_SMEM = (DIM * WS + 2 * TM * AS) * sizeof(uint32_t);  // 200KB
    if (!init_done) {
        cudaFuncSetAttribute(k_gemm, cudaFuncAttributeMaxDynamicSharedMemorySize, GEMM_SMEM);
        cudaStreamCreateWithFlags(&s2, cudaStreamNonBlocking);
        cudaEventCreateWithFlags(&ev_fork, cudaEventDisableTiming);
        cudaEventCreateWithFlags(&ev_join, cudaEventDisableTiming);
        cudaEventCreateWithFlags(&ev_g2, cudaEventDisableTiming);
        cudaEventCreateWithFlags(&ev_c0, cudaEventDisableTiming);
        cudaEventCreateWithFlags(&ev_c1, cudaEventDisableTiming);
        init_done = true;
    }
    const int GEMM_GRID = 148;

    float* g_h_p;   cudaGetSymbolAddress((void**)&g_h_p, g_h);
    float* g_z_p;   cudaGetSymbolAddress((void**)&g_z_p, g_z);
    float* g_h2_p;  cudaGetSymbolAddress((void**)&g_h2_p, g_h2);

    // fork: CSR build on s2, GEMM-1 on main (gemm1 fully hidden behind CSR)
    cudaEventRecord(ev_fork, 0);
    cudaStreamWaitEvent(s2, ev_fork, 0);

    k_init<<<gN, T, 0, s2>>>(n);
    k_count<<<gE, T, 0, s2>>>(dst, ew, e);
    k_scan1<<<nScanBlk, 1024, 0, s2>>>(n);
    k_gemm<<<GEMM_GRID, GEMM_T, GEMM_SMEM>>>(x, W1, g_h_p, n);
    k_scan2<<<1, 128, 0, s2>>>(nScanBlk, n, e);
    k_scan3<<<gN, T, 0, s2>>>(n);
    k_reorder<<<gE, T, 0, s2>>>(src, dst, ew, e);
    cudaEventRecord(ev_join, s2);
    cudaStreamWaitEvent(0, ev_join, 0);

    // 2-chunk agg1 || gemm2 overlap. gemm2 writes g_h2 (g_h stays intact for
    // agg1's full-range gather).
    const int half = (n + 1) / 2;
    {
        int gWc = (half * 32 + T - 1) / T;
        k_agg<<<gWc, T>>>(g_h_p, b1, g_z_p, 0, half);
        cudaEventRecord(ev_c0, 0);
        cudaStreamWaitEvent(s2, ev_c0, 0);
        k_gemm<<<GEMM_GRID, GEMM_T, GEMM_SMEM, s2>>>(g_z_p, W2, g_h2_p, half);

        int nodes1 = n - half;
        int gWc1 = (nodes1 * 32 + T - 1) / T;
        k_agg<<<gWc1, T>>>(g_h_p, b1, g_z_p, half, n);
        cudaEventRecord(ev_c1, 0);
        cudaStreamWaitEvent(s2, ev_c1, 0);
        k_gemm<<<GEMM_GRID, GEMM_T, GEMM_SMEM, s2>>>(
            g_z_p + (size_t)half * DIM, W2, g_h2_p + (size_t)half * DIM, nodes1);
    }
    cudaEventRecord(ev_g2, s2);
    cudaStreamWaitEvent(0, ev_g2, 0);

    // layer 2 agg (full range), gathers from g_h2
    int gW = (n * 32 + T - 1) / T;
    k_agg<<<gW, T>>>(g_h2_p, b2, out, 0, n);
}

// round 12
// speedup vs baseline: 1.1554x; 1.0290x over previous
#include <cuda_runtime.h>
#include <cuda_fp16.h>
#include <cstdint>

#define N_NODES 50000
#define N_EDGES 800000
#define DIM 128
#define DIM4 32
#define AS 132      // A smem stride (floats)
#define WS 136      // W smem stride (floats)
#define TM 128      // gemm tile rows
#define GEMM_T 512  // gemm threads

// Scratch (allocation-free: __device__ globals)
__device__ __half g_h[N_NODES * DIM];   // layer-1 gemm out (fp16 gather src)
__device__ float  g_z[N_NODES * DIM];   // layer-1 activations (fp32, gemm2 in)
__device__ __half g_h2[N_NODES * DIM];  // layer-2 gemm out (fp16 gather src)
__device__ float g_deg[N_NODES];
__device__ float g_dinv[N_NODES];
__device__ int   g_cnt[N_NODES];
__device__ int   g_cursor[N_NODES];
__device__ int   g_rowstart[N_NODES + 1];
__device__ int   g_blocksums[128];
__device__ int2  g_edges[N_EDGES];

// ---------------------------------------------------------------------------
__global__ void k_init(int n) {
    int i = blockIdx.x * blockDim.x + threadIdx.x;
    if (i < n) { g_deg[i] = 1.0f; g_cnt[i] = 0; g_cursor[i] = 0; }
}

__global__ void k_count(const int* __restrict__ dst, const float* __restrict__ ew, int e) {
    int i = blockIdx.x * blockDim.x + threadIdx.x;
    if (i < e) {
        int d = dst[i];
        atomicAdd(&g_deg[d], ew[i]);
        atomicAdd(&g_cnt[d], 1);
    }
}

// ---------------------------------------------------------------------------
__device__ __forceinline__ int warp_incl_scan(int x, int lane) {
    #pragma unroll
    for (int o = 1; o < 32; o <<= 1) {
        int y = __shfl_up_sync(0xffffffffu, x, o);
        if (lane >= o) x += y;
    }
    return x;
}

// scan phase 1 (+ fused dinv)
__global__ void k_scan1(int n) {
    __shared__ int warpsums[32];
    const int lane = threadIdx.x & 31;
    const int warp = threadIdx.x >> 5;
    int i = blockIdx.x * 1024 + threadIdx.x;
    if (i < n) g_dinv[i] = rsqrtf(g_deg[i]);
    int v = (i < n) ? g_cnt[i] : 0;
    int x = warp_incl_scan(v, lane);
    if (lane == 31) warpsums[warp] = x;
    __syncthreads();
    if (threadIdx.x < 32) {
        int s = warpsums[threadIdx.x];
        int xs = warp_incl_scan(s, threadIdx.x);
        warpsums[threadIdx.x] = xs - s;
    }
    __syncthreads();
    int excl = (x - v) + warpsums[warp];
    if (i < n) g_rowstart[i] = excl;
    if (threadIdx.x == 1023) g_blocksums[blockIdx.x] = excl + v;
}

__global__ void k_scan2(int nblocks, int n, int e) {
    __shared__ int tmp[128];
    const int lane = threadIdx.x & 31;
    if (threadIdx.x < 128) tmp[threadIdx.x] = (threadIdx.x < nblocks) ? g_blocksums[threadIdx.x] : 0;
    __syncthreads();
    if (threadIdx.x < 32) {
        int carry = 0;
        for (int c = 0; c < 128; c += 32) {
            int v = tmp[c + lane];
            int x = warp_incl_scan(v, lane);
            tmp[c + lane] = (x - v) + carry;
            carry += __shfl_sync(0xffffffffu, x, 31);
        }
    }
    __syncthreads();
    if (threadIdx.x < 128 && threadIdx.x < nblocks) g_blocksums[threadIdx.x] = tmp[threadIdx.x];
    if (threadIdx.x == 0) g_rowstart[n] = e;
}

__global__ void k_scan3(int n) {
    int i = blockIdx.x * blockDim.x + threadIdx.x;
    if (i < n) g_rowstart[i] += g_blocksums[i >> 10];
}

__global__ void k_reorder(const int* __restrict__ src, const int* __restrict__ dst,
                          const float* __restrict__ ew, int e) {
    int i = blockIdx.x * blockDim.x + threadIdx.x;
    if (i < e) {
        int s = src[i];
        int d = dst[i];
        float nrm = g_dinv[s] * ew[i] * g_dinv[d];
        int p = g_rowstart[d] + atomicAdd(&g_cursor[d], 1);
        g_edges[p] = make_int2(s, __float_as_int(nrm));
    }
}

// ---------------------------------------------------------------------------
// tf32 tensor GEMM (v3): 512 thr / 16 warps (8m x 2n), warp tile 16x64.
// Persistent, cp.async double-buffered A, 128x128 block tile.
// Epilogue writes fp16 (RN) — output is a gather source.
// ---------------------------------------------------------------------------
__device__ __forceinline__ uint32_t f2tf32(float v) {
    uint32_t o;
    asm("cvt.rna.tf32.f32 %0, %1;" : "=r"(o) : "f"(v));
    return o;
}

__device__ __forceinline__ void mma_tf32(float* c, const uint32_t* a,
                                         uint32_t b0, uint32_t b1) {
    asm volatile(
        "mma.sync.aligned.m16n8k8.row.col.f32.tf32.tf32.f32 "
        "{%0,%1,%2,%3}, {%4,%5,%6,%7}, {%8,%9}, {%0,%1,%2,%3};"
        : "+f"(c[0]), "+f"(c[1]), "+f"(c[2]), "+f"(c[3])
        : "r"(a[0]), "r"(a[1]), "r"(a[2]), "r"(a[3]), "r"(b0), "r"(b1));
}

__device__ __forceinline__ void load_tileA(float* dst, const float* __restrict__ in,
                                           int t, int n, int tid) {
    int row0 = t * TM;
    #pragma unroll 2
    for (int i = tid; i < TM * 32; i += GEMM_T) {
        int r = i >> 5, c = (i & 31) << 2;
        float* d = dst + r * AS + c;
        if (row0 + r < n) {
            uint32_t s = (uint32_t)__cvta_generic_to_shared(d);
            asm volatile("cp.async.cg.shared.global [%0], [%1], 16;"
                         :: "r"(s), "l"(in + (size_t)(row0 + r) * DIM + c));
        } else {
            *(float4*)d = make_float4(0.f, 0.f, 0.f, 0.f);
        }
    }
}

__global__ void __launch_bounds__(GEMM_T, 1)
k_gemm(const float* __restrict__ in, const float* __restrict__ W,
       __half* __restrict__ out, int n) {
    extern __shared__ uint32_t smem[];
    uint32_t* Ws = smem;                                  // [128][WS] tf32
    float* As0 = (float*)(smem + DIM * WS);               // [128][AS] fp32
    float* As1 = As0 + TM * AS;

    const int tid  = threadIdx.x;
    const int lane = tid & 31;
    const int warp = tid >> 5;
    const int warp_m = (warp & 7) * 16;
    const int warp_n = (warp >> 3) * 64;
    const int ntiles = (n + TM - 1) / TM;

    // stage W -> tf32 smem
    for (int i = tid; i < DIM * DIM4; i += GEMM_T) {
        int k = i >> 5, c4 = (i & 31) << 2;
        float4 v = ((const float4*)W)[i];
        uint32_t* p = Ws + k * WS + c4;
        p[0] = f2tf32(v.x); p[1] = f2tf32(v.y); p[2] = f2tf32(v.z); p[3] = f2tf32(v.w);
    }

    int t = blockIdx.x;
    if (t < ntiles) {
        load_tileA(As0, in, t, n, tid);
        asm volatile("cp.async.commit_group;");
    }

    int buf = 0;
    const int ar  = lane >> 2;
    const int akc = lane & 3;

    for (; t < ntiles; t += gridDim.x) {
        int tn = t + gridDim.x;
        if (tn < ntiles) {
            load_tileA(buf ? As0 : As1, in, tn, n, tid);
            asm volatile("cp.async.commit_group;");
            asm volatile("cp.async.wait_group 1;");
        } else {
            asm volatile("cp.async.wait_group 0;");
        }
        __syncthreads();   // also covers W staging on first iteration

        const float* A = buf ? As1 : As0;
        float acc[8][4];
        #pragma unroll
        for (int nt = 0; nt < 8; nt++)
            #pragma unroll
            for (int q = 0; q < 4; q++) acc[nt][q] = 0.0f;

        #pragma unroll
        for (int ks = 0; ks < 16; ks++) {
            const int k0 = ks * 8;
            uint32_t a[4];
            {
                int r = warp_m + ar;
                a[0] = f2tf32(A[r * AS + k0 + akc]);
                a[1] = f2tf32(A[(r + 8) * AS + k0 + akc]);
                a[2] = f2tf32(A[r * AS + k0 + akc + 4]);
                a[3] = f2tf32(A[(r + 8) * AS + k0 + akc + 4]);
            }
            #pragma unroll
            for (int nt = 0; nt < 8; nt++) {
                int bn = warp_n + nt * 8 + (lane >> 2);
                int bk = k0 + (lane & 3);
                uint32_t b0 = Ws[bk * WS + bn];
                uint32_t b1 = Ws[(bk + 4) * WS + bn];
                mma_tf32(acc[nt], a, b0, b1);
            }
        }

        int row0 = t * TM;
        int rbase = row0 + warp_m + (lane >> 2);
        #pragma unroll
        for (int nt = 0; nt < 8; nt++) {
            int col = warp_n + nt * 8 + 2 * (lane & 3);
            __half2 p0, p1;
            p0.x = __float2half_rn(acc[nt][0]);
            p0.y = __float2half_rn(acc[nt][1]);
            p1.x = __float2half_rn(acc[nt][2]);
            p1.y = __float2half_rn(acc[nt][3]);
            if (rbase < n)
                *(__half2*)(out + (size_t)rbase * DIM + col) = p0;
            if (rbase + 8 < n)
                *(__half2*)(out + (size_t)(rbase + 8) * DIM + col) = p1;
        }
        __syncthreads();   // tile buffer free for next prefetch
        buf ^= 1;
    }
}

// ---------------------------------------------------------------------------
// Gather-aggregate v3: fp16 gather source (halved traffic), fp32 accumulate,
// warp-uniform edge loads (no shuffles), unroll 8.
// Lane owns 4 consecutive cols = one 8B uint2 of fp16x4.
// ---------------------------------------------------------------------------
__device__ __forceinline__ float4 h4_to_f4(uint2 u) {
    __half2 p0 = *(__half2*)&u.x;
    __half2 p1 = *(__half2*)&u.y;
    float2 f0 = __half22float2(p0);
    float2 f1 = __half22float2(p1);
    return make_float4(f0.x, f0.y, f1.x, f1.y);
}

__global__ void k_agg(const __half* __restrict__ h, const float* __restrict__ b,
                      float* __restrict__ out, int node0, int node1) {
    int t = blockIdx.x * blockDim.x + threadIdx.x;
    int node = node0 + (t >> 5);
    int lane = t & 31;
    if (node >= node1) return;

    int beg = g_rowstart[node];
    int end = g_rowstart[node + 1];

    float di = g_dinv[node];
    float sl = di * di;
    float4 hv = h4_to_f4(*(const uint2*)(h + (size_t)node * DIM + lane * 4));
    float4 acc = make_float4(hv.x * sl, hv.y * sl, hv.z * sl, hv.w * sl);

    int j = beg;
    for (; j + 8 <= end; j += 8) {
        int2 ed[8];
        #pragma unroll
        for (int q = 0; q < 8; q++) ed[q] = g_edges[j + q];
        uint2 v[8];
        #pragma unroll
        for (int q = 0; q < 8; q++)
            v[q] = *(const uint2*)(h + (size_t)ed[q].x * DIM + lane * 4);
        #pragma unroll
        for (int q = 0; q < 8; q++) {
            float nr = __int_as_float(ed[q].y);
            float4 f = h4_to_f4(v[q]);
            acc.x = fmaf(nr, f.x, acc.x);
            acc.y = fmaf(nr, f.y, acc.y);
            acc.z = fmaf(nr, f.z, acc.z);
            acc.w = fmaf(nr, f.w, acc.w);
        }
    }
    for (; j < end; j++) {
        int2 ed = g_edges[j];
        float nr = __int_as_float(ed.y);
        float4 f = h4_to_f4(*(const uint2*)(h + (size_t)ed.x * DIM + lane * 4));
        acc.x = fmaf(nr, f.x, acc.x);
        acc.y = fmaf(nr, f.y, acc.y);
        acc.z = fmaf(nr, f.z, acc.z);
        acc.w = fmaf(nr, f.w, acc.w);
    }

    float4 bv = ((const float4*)b)[lane];
    float4 o;
    o.x = fmaxf(acc.x + bv.x, 0.0f);
    o.y = fmaxf(acc.y + bv.y, 0.0f);
    o.z = fmaxf(acc.z + bv.z, 0.0f);
    o.w = fmaxf(acc.w + bv.w, 0.0f);
    ((float4*)(out + (size_t)node * DIM))[lane] = o;
}

// ---------------------------------------------------------------------------
extern "C" void kernel_launch(void* const* d_in, const int* in_sizes, int n_in,
                              void* d_out, int out_size) {
    const float* x   = (const float*)d_in[0];
    const int*   ei  = (const int*)d_in[1];
    const float* ew  = (const float*)d_in[2];
    const float* W1  = (const float*)d_in[3];
    const float* b1  = (const float*)d_in[4];
    const float* W2  = (const float*)d_in[5];
    const float* b2  = (const float*)d_in[6];
    float* out = (float*)d_out;

    const int n = in_sizes[0] / DIM;
    const int e = in_sizes[2];
    const int* src = ei;
    const int* dst = ei + e;

    const int T = 256;
    const int gN = (n + T - 1) / T;
    const int gE = (e + T - 1) / T;
    const int nScanBlk = (n + 1023) / 1024;

    static cudaStream_t s2 = nullptr;
    static cudaEvent_t ev_fork = nullptr, ev_join = nullptr, ev_g2 = nullptr;
    static cudaEvent_t ev_c0 = nullptr, ev_c1 = nullptr;
    static bool init_done = false;
    const int GEMM_SMEM = (DIM * WS + 2 * TM * AS) * sizeof(uint32_t);  // 200KB
    if (!init_done) {
        cudaFuncSetAttribute(k_gemm, cudaFuncAttributeMaxDynamicSharedMemorySize, GEMM_SMEM);
        cudaStreamCreateWithFlags(&s2, cudaStreamNonBlocking);
        cudaEventCreateWithFlags(&ev_fork, cudaEventDisableTiming);
        cudaEventCreateWithFlags(&ev_join, cudaEventDisableTiming);
        cudaEventCreateWithFlags(&ev_g2, cudaEventDisableTiming);
        cudaEventCreateWithFlags(&ev_c0, cudaEventDisableTiming);
        cudaEventCreateWithFlags(&ev_c1, cudaEventDisableTiming);
        init_done = true;
    }
    const int GEMM_GRID = 148;

    __half* g_h_p;   cudaGetSymbolAddress((void**)&g_h_p, g_h);
    float*  g_z_p;   cudaGetSymbolAddress((void**)&g_z_p, g_z);
    __half* g_h2_p;  cudaGetSymbolAddress((void**)&g_h2_p, g_h2);

    // fork: CSR build on s2, GEMM-1 on main (gemm1 fully hidden behind CSR)
    cudaEventRecord(ev_fork, 0);
    cudaStreamWaitEvent(s2, ev_fork, 0);

    k_init<<<gN, T, 0, s2>>>(n);
    k_count<<<gE, T, 0, s2>>>(dst, ew, e);
    k_scan1<<<nScanBlk, 1024, 0, s2>>>(n);
    k_gemm<<<GEMM_GRID, GEMM_T, GEMM_SMEM>>>(x, W1, g_h_p, n);
    k_scan2<<<1, 128, 0, s2>>>(nScanBlk, n, e);
    k_scan3<<<gN, T, 0, s2>>>(n);
    k_reorder<<<gE, T, 0, s2>>>(src, dst, ew, e);
    cudaEventRecord(ev_join, s2);
    cudaStreamWaitEvent(0, ev_join, 0);

    // 2-chunk agg1 || gemm2 overlap. gemm2 writes g_h2 (g_h stays intact for
    // agg1's full-range gather).
    const int half = (n + 1) / 2;
    {
        int gWc = (half * 32 + T - 1) / T;
        k_agg<<<gWc, T>>>(g_h_p, b1, g_z_p, 0, half);
        cudaEventRecord(ev_c0, 0);
        cudaStreamWaitEvent(s2, ev_c0, 0);
        k_gemm<<<GEMM_GRID, GEMM_T, GEMM_SMEM, s2>>>(g_z_p, W2, g_h2_p, half);

        int nodes1 = n - half;
        int gWc1 = (nodes1 * 32 + T - 1) / T;
        k_agg<<<gWc1, T>>>(g_h_p, b1, g_z_p, half, n);
        cudaEventRecord(ev_c1, 0);
        cudaStreamWaitEvent(s2, ev_c1, 0);
        k_gemm<<<GEMM_GRID, GEMM_T, GEMM_SMEM, s2>>>(
            g_z_p + (size_t)half * DIM, W2, g_h2_p + (size_t)half * DIM, nodes1);
    }
    cudaEventRecord(ev_g2, s2);
    cudaStreamWaitEvent(0, ev_g2, 0);

    // layer 2 agg (full range), gathers from g_h2
    int gW = (n * 32 + T - 1) / T;
    k_agg<<<gW, T>>>(g_h2_p, b2, out, 0, n);
}